// round 10
// baseline (speedup 1.0000x reference)
#include <cuda_runtime.h>
#include <cstdint>
#include <math.h>

#define BDIM 256
#define LATD 20
#define HID 128
#define GDIM 25000
#define CDIM 7
#define GBD 1000
#define NS (BDIM * GBD)   // 256000 bins total

// Output layout (float32, flattened tuple in order):
//   mu      [256,25000]    @ 0
//   theta   [256,25000]    @ 6400000
//   pi_drop [256,25000]    @ 12800000
//   sample  [256,25000]    @ 19200000
//   pi      [256,25000,7]  @ 25600000
#define OFF_THETA  6400000
#define OFF_PDROP 12800000
#define OFF_SAMP  19200000
#define OFF_PI    25600000

// Scratch (device globals: no allocation allowed)
__device__ float g_xT[HID * BDIM];      // x transposed: [h][b]
__device__ float g_rlog[CDIM * NS];     // rho logits [c][b*GB]
__device__ float4 g_pib[NS * 4];        // per-bin struct: {pi[7], ipi[7], pad2}

// Packed fp32x2 ops (sm_103a FFMA2 — only reachable via PTX)
#define FMA_F32X2(d, a, b, c) \
    asm("fma.rn.f32x2 %0, %1, %2, %3;" : "=l"(d) : "l"(a), "l"(b), "l"(c))
#define PACK_DUP_F32X2(d, s) \
    asm("mov.b64 %0, {%1, %1};" : "=l"(d) : "r"(__float_as_uint(s)))

// ---------------------------------------------------------------------------
// JAX threefry2x32, key = (0, 42), 20 rounds, partitionable mode:
//   bits32(i) = o0 ^ o1 where (o0,o1) = threefry(key, 0, i)
// ---------------------------------------------------------------------------
__device__ __forceinline__ unsigned threefry_xor(unsigned x0, unsigned x1) {
    const unsigned ks0 = 0u;
    const unsigned ks1 = 42u;
    const unsigned ks2 = 0x1BD11BDAu ^ 0u ^ 42u;
    x0 += ks0; x1 += ks1;
#define TFR(r) { x0 += x1; x1 = __funnelshift_l(x1, x1, (r)); x1 ^= x0; }
    TFR(13) TFR(15) TFR(26) TFR(6)
    x0 += ks1; x1 += ks2 + 1u;
    TFR(17) TFR(29) TFR(16) TFR(24)
    x0 += ks2; x1 += ks0 + 2u;
    TFR(13) TFR(15) TFR(26) TFR(6)
    x0 += ks0; x1 += ks1 + 3u;
    TFR(17) TFR(29) TFR(16) TFR(24)
    x0 += ks1; x1 += ks2 + 4u;
    TFR(13) TFR(15) TFR(26) TFR(6)
    x0 += ks2; x1 += ks0 + 5u;
#undef TFR
    return x0 ^ x1;
}

__device__ __forceinline__ float u01(unsigned bits) {
    return __uint_as_float((bits >> 9) | 0x3f800000u) - 1.0f;
}

// ---------------------------------------------------------------------------
// K1: tiny MLP.  grid(256), block(128).  Writes x transposed -> g_xT[h][b]
// ---------------------------------------------------------------------------
__global__ void mlp_kernel(const float* __restrict__ z,
                           const float* __restrict__ w0, const float* __restrict__ b0,
                           const float* __restrict__ gm0, const float* __restrict__ be0,
                           const float* __restrict__ m0, const float* __restrict__ v0,
                           const float* __restrict__ w1, const float* __restrict__ b1,
                           const float* __restrict__ gm1, const float* __restrict__ be1,
                           const float* __restrict__ m1, const float* __restrict__ v1) {
    __shared__ float zs[LATD];
    __shared__ float s0[HID];
    const int b = blockIdx.x, h = threadIdx.x;
    if (h < LATD) zs[h] = z[b * LATD + h];
    __syncthreads();
    float t = b0[h];
#pragma unroll
    for (int k = 0; k < LATD; k++) t = fmaf(zs[k], w0[k * HID + h], t);
    t = (t - m0[h]) * rsqrtf(v0[h] + 1e-3f) * gm0[h] + be0[h];
    s0[h] = fmaxf(t, 0.0f);
    __syncthreads();
    float t2 = b1[h];
#pragma unroll
    for (int k = 0; k < HID; k++) t2 = fmaf(s0[k], w1[k * HID + h], t2);
    t2 = (t2 - m1[h]) * rsqrtf(v1[h] + 1e-3f) * gm1[h] + be1[h];
    g_xT[h * BDIM + b] = fmaxf(t2, 0.0f);
}

// ---------------------------------------------------------------------------
// GEMM core: one 128x64 output tile of X[256,128] @ W[128,N] + bias.
// 256 threads, 8x4 per thread. W staged in CALLER-OWNED 32KB smem (single
// buffer shared across template instantiations — avoids the 66KB double
// allocation that capped occupancy at 3 blocks/SM). x via L1 broadcast.
// ---------------------------------------------------------------------------
template <int ACT>
__device__ __forceinline__ void gemm_tile(float* __restrict__ Ws,  // [128*64]
                                          const float* __restrict__ W,
                                          const float* __restrict__ bias,
                                          float* __restrict__ out,
                                          int N, int n0, int m0) {
    const int tid = threadIdx.x;
#pragma unroll
    for (int t = 0; t < 8; t++) {
        int f = tid + t * 256;
        int k = f >> 4;
        int j4 = (f & 15) << 2;
        int n = n0 + j4;
        float4 v = make_float4(0.f, 0.f, 0.f, 0.f);
        if (n < N) v = *reinterpret_cast<const float4*>(W + (size_t)k * N + n);
        *reinterpret_cast<float4*>(Ws + k * 64 + j4) = v;
    }
    __syncthreads();
    const int tn = (tid & 15) << 2;   // 16 n-groups * 4
    const int tm = (tid >> 4) << 3;   // 16 m-groups * 8 = 128 rows
    unsigned long long acc[8][2] = {};
    const float* xb = g_xT + m0 + tm;
#pragma unroll 2
    for (int k = 0; k < 128; k++) {
        const float4 av0 = __ldg(reinterpret_cast<const float4*>(xb + (size_t)k * BDIM));
        const float4 av1 = __ldg(reinterpret_cast<const float4*>(xb + (size_t)k * BDIM + 4));
        const unsigned long long* bp =
            reinterpret_cast<const unsigned long long*>(Ws + k * 64 + tn);
        const unsigned long long b01 = bp[0];
        const unsigned long long b23 = bp[1];
        const float a[8] = {av0.x, av0.y, av0.z, av0.w, av1.x, av1.y, av1.z, av1.w};
#pragma unroll
        for (int i = 0; i < 8; i++) {
            unsigned long long ap;
            PACK_DUP_F32X2(ap, a[i]);
            FMA_F32X2(acc[i][0], ap, b01, acc[i][0]);
            FMA_F32X2(acc[i][1], ap, b23, acc[i][1]);
        }
    }
    const int n = n0 + tn;
    if (n < N) {
        const float4 bv = *reinterpret_cast<const float4*>(bias + n);
#pragma unroll
        for (int i = 0; i < 8; i++) {
            const int m = m0 + tm + i;
            float2 lo = *reinterpret_cast<float2*>(&acc[i][0]);
            float2 hi = *reinterpret_cast<float2*>(&acc[i][1]);
            float4 r;
            r.x = lo.x + bv.x;
            r.y = lo.y + bv.y;
            r.z = hi.x + bv.z;
            r.w = hi.y + bv.w;
            if (ACT == 1) {
                r.x = __expf(r.x); r.y = __expf(r.y);
                r.z = __expf(r.z); r.w = __expf(r.w);
            }
            *reinterpret_cast<float4*>(out + (size_t)m * N + n) = r;
        }
    }
}

// K2a: theta (exp) + pi_drop in one launch. z=0 -> theta, z=1 -> pi_drop.
__global__ void __launch_bounds__(256, 4) big_gemm_kernel(
        const float* __restrict__ wr, const float* __restrict__ br,
        const float* __restrict__ wd, const float* __restrict__ bd,
        float* __restrict__ out) {
    __shared__ float Ws[128 * 64];  // single buffer shared by both branches
    const int n0 = blockIdx.x * 64;
    const int m0 = blockIdx.y * 128;
    if (blockIdx.z == 0)
        gemm_tile<1>(Ws, wr, br, out + OFF_THETA, GDIM, n0, m0);
    else
        gemm_tile<0>(Ws, wd, bd, out + OFF_PDROP, GDIM, n0, m0);
}

// K2b: all 7 rho heads in one launch. z = copy-number state c.
__global__ void __launch_bounds__(256, 4) rho_gemm_kernel(
        const float* __restrict__ wrho, const float* __restrict__ brho,
        float* __restrict__ rlog) {
    __shared__ float Ws[128 * 64];
    const int c = blockIdx.z;
    const int n0 = blockIdx.x * 64;
    const int m0 = blockIdx.y * 128;
    gemm_tile<0>(Ws, wrho + (size_t)c * HID * GBD, brho + (size_t)c * GBD,
                 rlog + (size_t)c * BDIM * GBD, GBD, n0, m0);
}

// ---------------------------------------------------------------------------
// K3: softmax over the C=7 copy-number states (accurate expf; pi feeds the
// sampler's ordering with no fallback protection). Writes one 64B struct
// per bin: {pi[0..6], ipi[0..6], pad, pad} as 4 x float4.
// ---------------------------------------------------------------------------
__global__ void rho_softmax_kernel() {
    const int i = blockIdx.x * 256 + threadIdx.x;  // over B*GB = 256000
    if (i >= NS) return;
    float l[CDIM];
    float mx = -3.402823466e38f;
#pragma unroll
    for (int c = 0; c < CDIM; c++) {
        l[c] = g_rlog[c * NS + i];
        mx = fmaxf(mx, l[c]);
    }
    float s = 0.0f;
#pragma unroll
    for (int c = 0; c < CDIM; c++) { l[c] = expf(l[c] - mx); s += l[c]; }
    float v[16];
#pragma unroll
    for (int c = 0; c < CDIM; c++) {
        const float pe = l[c] / s;
        v[c] = pe;
        v[7 + c] = 1.0f / (pe + 1e-20f);
    }
    v[14] = 0.f; v[15] = 0.f;
    float4* dst = &g_pib[(size_t)i * 4];
    dst[0] = make_float4(v[0],  v[1],  v[2],  v[3]);
    dst[1] = make_float4(v[4],  v[5],  v[6],  v[7]);
    dst[2] = make_float4(v[8],  v[9],  v[10], v[11]);
    dst[3] = make_float4(v[12], v[13], v[14], v[15]);
}

// ---------------------------------------------------------------------------
// K4: Gumbel straight-through sampler. 2 adjacent genes per thread.
// Fast path: argmin_c nl_c * ipi_c with nl via MUFU __logf (off the fma pipe).
// Robust fallback: if top-2 gap < 1e-4*w2 + 4e-6 (>=20x worst-case __logf
// error), redo ordering with the exact accurate-logf reference formula.
// (Measured R7: 141.6us, alu=89.7% — at its threefry alu floor. Unchanged.)
// ---------------------------------------------------------------------------
__global__ void __launch_bounds__(256) gumbel_kernel(const float* __restrict__ ws,
                                                     const float* __restrict__ bs,
                                                     float* __restrict__ out) {
    const int t = blockIdx.x * 256 + threadIdx.x;
    const int g0 = t * 2;
    if (g0 >= GDIM) return;
    const int b = blockIdx.y;  // 0..255
    const size_t e0 = (size_t)b * GDIM + g0;

    float buf[14];
    float sm[2];
#pragma unroll
    for (int q = 0; q < 2; q++) {
        const int g = g0 + q;
        const int i0 = b * GBD + g / 25;
        const float4* pbp = &g_pib[(size_t)i0 * 4];
        const float4 L0 = __ldg(pbp + 0);
        const float4 L1 = __ldg(pbp + 1);
        const float4 L2 = __ldg(pbp + 2);
        const float4 L3 = __ldg(pbp + 3);
        const float pi[CDIM] = {L0.x, L0.y, L0.z, L0.w, L1.x, L1.y, L1.z};
        const float ip[CDIM] = {L1.w, L2.x, L2.y, L2.z, L2.w, L3.x, L3.y};
        const unsigned base = ((unsigned)b * (unsigned)GDIM + (unsigned)g) * 7u;
        float u[CDIM];
        float w1 = 3.402823466e38f, w2 = 3.402823466e38f;
        int amin = 0;
#pragma unroll
        for (int c = 0; c < CDIM; c++) {
            u[c] = u01(threefry_xor(0u, base + (unsigned)c));
            const float w = -__logf(u[c] + 1e-20f) * ip[c];
            if (w < w1) { w2 = w1; w1 = w; amin = c; }
            else if (w < w2) { w2 = w; }
        }
        if (w2 - w1 < 1e-4f * w2 + 4e-6f) {
            // exact reference-formula ordering (accurate logf) for near-ties
            float best = -3.402823466e38f;
            amin = 0;
#pragma unroll
            for (int c = 0; c < CDIM; c++) {
                const float nle = -logf(u[c] + 1e-20f) + 1e-20f;
                const float l = logf(pi[c] + 1e-20f) - logf(nle);
                if (l > best) { best = l; amin = c; }
            }
        }
        sm[q] = (float)amin;
#pragma unroll
        for (int c = 0; c < CDIM; c++) buf[q * CDIM + c] = pi[c];
    }

    // pi: 14 contiguous floats (genes g0, g0+1), 8B-aligned -> 7 x STG.64
    float2* pio = reinterpret_cast<float2*>(out + OFF_PI + e0 * 7);
#pragma unroll
    for (int j = 0; j < 7; j++)
        pio[j] = make_float2(buf[2 * j], buf[2 * j + 1]);

    const float2 wsv = *reinterpret_cast<const float2*>(ws + g0);
    const float2 bsv = *reinterpret_cast<const float2*>(bs + g0);
    *reinterpret_cast<float2*>(out + OFF_SAMP + e0) = make_float2(sm[0], sm[1]);
    float2 muv;
    muv.x = 1.0f / (1.0f + __expf(-fmaf(sm[0], wsv.x, bsv.x)));
    muv.y = 1.0f / (1.0f + __expf(-fmaf(sm[1], wsv.y, bsv.y)));
    *reinterpret_cast<float2*>(out + e0) = muv;
}

// ---------------------------------------------------------------------------
extern "C" void kernel_launch(void* const* d_in, const int* in_sizes, int n_in,
                              void* d_out, int out_size) {
    const float* z   = (const float*)d_in[0];
    const float* w0  = (const float*)d_in[1];
    const float* b0  = (const float*)d_in[2];
    const float* gm0 = (const float*)d_in[3];
    const float* be0 = (const float*)d_in[4];
    const float* m0  = (const float*)d_in[5];
    const float* v0  = (const float*)d_in[6];
    const float* w1  = (const float*)d_in[7];
    const float* b1  = (const float*)d_in[8];
    const float* gm1 = (const float*)d_in[9];
    const float* be1 = (const float*)d_in[10];
    const float* m1  = (const float*)d_in[11];
    const float* v1  = (const float*)d_in[12];
    const float* wr  = (const float*)d_in[13];
    const float* br  = (const float*)d_in[14];
    const float* wd  = (const float*)d_in[15];
    const float* bd  = (const float*)d_in[16];
    const float* wrho = (const float*)d_in[17];
    const float* brho = (const float*)d_in[18];
    const float* ws  = (const float*)d_in[19];
    const float* bs  = (const float*)d_in[20];
    float* out = (float*)d_out;

    float* rlog_ptr = nullptr;
    cudaGetSymbolAddress((void**)&rlog_ptr, g_rlog);

    // Order: mlp, rho, softmax, BIG_GEMM (position 4 -> ncu capture), gumbel.
    mlp_kernel<<<BDIM, HID>>>(z, w0, b0, gm0, be0, m0, v0,
                              w1, b1, gm1, be1, m1, v1);

    // all 7 rho heads: m-tile 128 -> grid (16, 2, 7)
    rho_gemm_kernel<<<dim3((GBD + 63) / 64, 2, CDIM), 256>>>(wrho, brho, rlog_ptr);

    rho_softmax_kernel<<<(NS + 255) / 256, 256>>>();

    // theta + pi_drop: m-tile 128 -> grid (391, 2, 2)
    big_gemm_kernel<<<dim3((GDIM + 63) / 64, 2, 2), 256>>>(wr, br, wd, bd, out);

    gumbel_kernel<<<dim3((GDIM / 2 + 255) / 256, 256), 256>>>(ws, bs, out);
}

// round 11
// speedup vs baseline: 1.0571x; 1.0571x over previous
#include <cuda_runtime.h>
#include <cstdint>
#include <math.h>

#define BDIM 256
#define LATD 20
#define HID 128
#define GDIM 25000
#define CDIM 7
#define GBD 1000
#define NS (BDIM * GBD)   // 256000 bins total

// Output layout (float32, flattened tuple in order):
//   mu      [256,25000]    @ 0
//   theta   [256,25000]    @ 6400000
//   pi_drop [256,25000]    @ 12800000
//   sample  [256,25000]    @ 19200000
//   pi      [256,25000,7]  @ 25600000
#define OFF_THETA  6400000
#define OFF_PDROP 12800000
#define OFF_SAMP  19200000
#define OFF_PI    25600000

// Scratch (device globals: no allocation allowed)
__device__ float g_xT[HID * BDIM];      // x transposed: [h][b]
__device__ float g_rlog[CDIM * NS];     // rho logits [c][b*GB]
__device__ float4 g_pib[NS * 4];        // per-bin struct: {pi[7], ipi[7], pad2}

// Packed fp32x2 ops (sm_103a FFMA2 — only reachable via PTX)
#define FMA_F32X2(d, a, b, c) \
    asm("fma.rn.f32x2 %0, %1, %2, %3;" : "=l"(d) : "l"(a), "l"(b), "l"(c))
#define PACK_DUP_F32X2(d, s) \
    asm("mov.b64 %0, {%1, %1};" : "=l"(d) : "r"(__float_as_uint(s)))

// ---------------------------------------------------------------------------
// JAX threefry2x32, key = (0, 42), 20 rounds, partitionable mode:
//   bits32(i) = o0 ^ o1 where (o0,o1) = threefry(key, 0, i)
// ---------------------------------------------------------------------------
__device__ __forceinline__ unsigned threefry_xor(unsigned x0, unsigned x1) {
    const unsigned ks0 = 0u;
    const unsigned ks1 = 42u;
    const unsigned ks2 = 0x1BD11BDAu ^ 0u ^ 42u;
    x0 += ks0; x1 += ks1;
#define TFR(r) { x0 += x1; x1 = __funnelshift_l(x1, x1, (r)); x1 ^= x0; }
    TFR(13) TFR(15) TFR(26) TFR(6)
    x0 += ks1; x1 += ks2 + 1u;
    TFR(17) TFR(29) TFR(16) TFR(24)
    x0 += ks2; x1 += ks0 + 2u;
    TFR(13) TFR(15) TFR(26) TFR(6)
    x0 += ks0; x1 += ks1 + 3u;
    TFR(17) TFR(29) TFR(16) TFR(24)
    x0 += ks1; x1 += ks2 + 4u;
    TFR(13) TFR(15) TFR(26) TFR(6)
    x0 += ks2; x1 += ks0 + 5u;
#undef TFR
    return x0 ^ x1;
}

__device__ __forceinline__ float u01(unsigned bits) {
    return __uint_as_float((bits >> 9) | 0x3f800000u) - 1.0f;
}

// ---------------------------------------------------------------------------
// K1: tiny MLP.  grid(256), block(128).  Writes x transposed -> g_xT[h][b]
// ---------------------------------------------------------------------------
__global__ void mlp_kernel(const float* __restrict__ z,
                           const float* __restrict__ w0, const float* __restrict__ b0,
                           const float* __restrict__ gm0, const float* __restrict__ be0,
                           const float* __restrict__ m0, const float* __restrict__ v0,
                           const float* __restrict__ w1, const float* __restrict__ b1,
                           const float* __restrict__ gm1, const float* __restrict__ be1,
                           const float* __restrict__ m1, const float* __restrict__ v1) {
    __shared__ float zs[LATD];
    __shared__ float s0[HID];
    const int b = blockIdx.x, h = threadIdx.x;
    if (h < LATD) zs[h] = z[b * LATD + h];
    __syncthreads();
    float t = b0[h];
#pragma unroll
    for (int k = 0; k < LATD; k++) t = fmaf(zs[k], w0[k * HID + h], t);
    t = (t - m0[h]) * rsqrtf(v0[h] + 1e-3f) * gm0[h] + be0[h];
    s0[h] = fmaxf(t, 0.0f);
    __syncthreads();
    float t2 = b1[h];
#pragma unroll
    for (int k = 0; k < HID; k++) t2 = fmaf(s0[k], w1[k * HID + h], t2);
    t2 = (t2 - m1[h]) * rsqrtf(v1[h] + 1e-3f) * gm1[h] + be1[h];
    g_xT[h * BDIM + b] = fmaxf(t2, 0.0f);
}

// ---------------------------------------------------------------------------
// GEMM core: one 128x64 output tile of X[256,128] @ W[128,N] + bias.
// 256 threads, 8x4 per thread. Software-pipelined: k+1's x (2x LDG.128) and
// W (1x LDS.128) are fetched while k's 16 FFMA2 issue — breaks the load->use
// stall chain that pinned issue at 36% regardless of occupancy (R8 vs R10).
// ---------------------------------------------------------------------------
template <int ACT>
__device__ __forceinline__ void gemm_tile(float* __restrict__ Ws,  // [128*64]
                                          const float* __restrict__ W,
                                          const float* __restrict__ bias,
                                          float* __restrict__ out,
                                          int N, int n0, int m0) {
    const int tid = threadIdx.x;
#pragma unroll
    for (int t = 0; t < 8; t++) {
        int f = tid + t * 256;
        int k = f >> 4;
        int j4 = (f & 15) << 2;
        int n = n0 + j4;
        float4 v = make_float4(0.f, 0.f, 0.f, 0.f);
        if (n < N) v = *reinterpret_cast<const float4*>(W + (size_t)k * N + n);
        *reinterpret_cast<float4*>(Ws + k * 64 + j4) = v;
    }
    __syncthreads();
    const int tn = (tid & 15) << 2;   // 16 n-groups * 4
    const int tm = (tid >> 4) << 3;   // 16 m-groups * 8 = 128 rows
    unsigned long long acc[8][2] = {};
    const float* xb = g_xT + m0 + tm;

    // prologue: fetch k = 0
    float4 av0 = __ldg(reinterpret_cast<const float4*>(xb));
    float4 av1 = __ldg(reinterpret_cast<const float4*>(xb + 4));
    float4 wv  = *reinterpret_cast<const float4*>(Ws + tn);

#pragma unroll 4
    for (int k = 0; k < 128; k++) {
        // prefetch k+1 (last iteration redundantly refetches k=127; unused)
        const int kn = (k < 127) ? (k + 1) : 127;
        const float* xn = xb + (size_t)kn * BDIM;
        float4 nav0 = __ldg(reinterpret_cast<const float4*>(xn));
        float4 nav1 = __ldg(reinterpret_cast<const float4*>(xn + 4));
        float4 nwv  = *reinterpret_cast<const float4*>(Ws + kn * 64 + tn);

        const unsigned long long b01 =
            reinterpret_cast<const unsigned long long*>(&wv)[0];
        const unsigned long long b23 =
            reinterpret_cast<const unsigned long long*>(&wv)[1];
        const float a[8] = {av0.x, av0.y, av0.z, av0.w,
                            av1.x, av1.y, av1.z, av1.w};
#pragma unroll
        for (int i = 0; i < 8; i++) {
            unsigned long long ap;
            PACK_DUP_F32X2(ap, a[i]);
            FMA_F32X2(acc[i][0], ap, b01, acc[i][0]);
            FMA_F32X2(acc[i][1], ap, b23, acc[i][1]);
        }
        av0 = nav0; av1 = nav1; wv = nwv;
    }

    const int n = n0 + tn;
    if (n < N) {
        const float4 bv = *reinterpret_cast<const float4*>(bias + n);
#pragma unroll
        for (int i = 0; i < 8; i++) {
            const int m = m0 + tm + i;
            float2 lo = *reinterpret_cast<float2*>(&acc[i][0]);
            float2 hi = *reinterpret_cast<float2*>(&acc[i][1]);
            float4 r;
            r.x = lo.x + bv.x;
            r.y = lo.y + bv.y;
            r.z = hi.x + bv.z;
            r.w = hi.y + bv.w;
            if (ACT == 1) {
                r.x = __expf(r.x); r.y = __expf(r.y);
                r.z = __expf(r.z); r.w = __expf(r.w);
            }
            *reinterpret_cast<float4*>(out + (size_t)m * N + n) = r;
        }
    }
}

// K2a: theta (exp) + pi_drop in one launch. z=0 -> theta, z=1 -> pi_drop.
__global__ void __launch_bounds__(256) big_gemm_kernel(
        const float* __restrict__ wr, const float* __restrict__ br,
        const float* __restrict__ wd, const float* __restrict__ bd,
        float* __restrict__ out) {
    __shared__ float Ws[128 * 64];  // single buffer shared by both branches
    const int n0 = blockIdx.x * 64;
    const int m0 = blockIdx.y * 128;
    if (blockIdx.z == 0)
        gemm_tile<1>(Ws, wr, br, out + OFF_THETA, GDIM, n0, m0);
    else
        gemm_tile<0>(Ws, wd, bd, out + OFF_PDROP, GDIM, n0, m0);
}

// K2b: all 7 rho heads in one launch. z = copy-number state c.
__global__ void __launch_bounds__(256) rho_gemm_kernel(
        const float* __restrict__ wrho, const float* __restrict__ brho,
        float* __restrict__ rlog) {
    __shared__ float Ws[128 * 64];
    const int c = blockIdx.z;
    const int n0 = blockIdx.x * 64;
    const int m0 = blockIdx.y * 128;
    gemm_tile<0>(Ws, wrho + (size_t)c * HID * GBD, brho + (size_t)c * GBD,
                 rlog + (size_t)c * BDIM * GBD, GBD, n0, m0);
}

// ---------------------------------------------------------------------------
// K3: softmax over the C=7 copy-number states (accurate expf; pi feeds the
// sampler's ordering with no fallback protection). Writes one 64B struct
// per bin: {pi[0..6], ipi[0..6], pad, pad} as 4 x float4.
// ---------------------------------------------------------------------------
__global__ void rho_softmax_kernel() {
    const int i = blockIdx.x * 256 + threadIdx.x;  // over B*GB = 256000
    if (i >= NS) return;
    float l[CDIM];
    float mx = -3.402823466e38f;
#pragma unroll
    for (int c = 0; c < CDIM; c++) {
        l[c] = g_rlog[c * NS + i];
        mx = fmaxf(mx, l[c]);
    }
    float s = 0.0f;
#pragma unroll
    for (int c = 0; c < CDIM; c++) { l[c] = expf(l[c] - mx); s += l[c]; }
    float v[16];
#pragma unroll
    for (int c = 0; c < CDIM; c++) {
        const float pe = l[c] / s;
        v[c] = pe;
        v[7 + c] = 1.0f / (pe + 1e-20f);
    }
    v[14] = 0.f; v[15] = 0.f;
    float4* dst = &g_pib[(size_t)i * 4];
    dst[0] = make_float4(v[0],  v[1],  v[2],  v[3]);
    dst[1] = make_float4(v[4],  v[5],  v[6],  v[7]);
    dst[2] = make_float4(v[8],  v[9],  v[10], v[11]);
    dst[3] = make_float4(v[12], v[13], v[14], v[15]);
}

// ---------------------------------------------------------------------------
// K4: Gumbel straight-through sampler. 2 adjacent genes per thread.
// Fast path: argmin_c nl_c * ipi_c with nl via MUFU __logf (off the fma pipe).
// Robust fallback: if top-2 gap < 1e-4*w2 + 4e-6 (>=20x worst-case __logf
// error), redo ordering with the exact accurate-logf reference formula.
// (Measured R7: 141.6us, alu=89.7% — at its threefry alu floor. Unchanged.)
// ---------------------------------------------------------------------------
__global__ void __launch_bounds__(256) gumbel_kernel(const float* __restrict__ ws,
                                                     const float* __restrict__ bs,
                                                     float* __restrict__ out) {
    const int t = blockIdx.x * 256 + threadIdx.x;
    const int g0 = t * 2;
    if (g0 >= GDIM) return;
    const int b = blockIdx.y;  // 0..255
    const size_t e0 = (size_t)b * GDIM + g0;

    float buf[14];
    float sm[2];
#pragma unroll
    for (int q = 0; q < 2; q++) {
        const int g = g0 + q;
        const int i0 = b * GBD + g / 25;
        const float4* pbp = &g_pib[(size_t)i0 * 4];
        const float4 L0 = __ldg(pbp + 0);
        const float4 L1 = __ldg(pbp + 1);
        const float4 L2 = __ldg(pbp + 2);
        const float4 L3 = __ldg(pbp + 3);
        const float pi[CDIM] = {L0.x, L0.y, L0.z, L0.w, L1.x, L1.y, L1.z};
        const float ip[CDIM] = {L1.w, L2.x, L2.y, L2.z, L2.w, L3.x, L3.y};
        const unsigned base = ((unsigned)b * (unsigned)GDIM + (unsigned)g) * 7u;
        float u[CDIM];
        float w1 = 3.402823466e38f, w2 = 3.402823466e38f;
        int amin = 0;
#pragma unroll
        for (int c = 0; c < CDIM; c++) {
            u[c] = u01(threefry_xor(0u, base + (unsigned)c));
            const float w = -__logf(u[c] + 1e-20f) * ip[c];
            if (w < w1) { w2 = w1; w1 = w; amin = c; }
            else if (w < w2) { w2 = w; }
        }
        if (w2 - w1 < 1e-4f * w2 + 4e-6f) {
            // exact reference-formula ordering (accurate logf) for near-ties
            float best = -3.402823466e38f;
            amin = 0;
#pragma unroll
            for (int c = 0; c < CDIM; c++) {
                const float nle = -logf(u[c] + 1e-20f) + 1e-20f;
                const float l = logf(pi[c] + 1e-20f) - logf(nle);
                if (l > best) { best = l; amin = c; }
            }
        }
        sm[q] = (float)amin;
#pragma unroll
        for (int c = 0; c < CDIM; c++) buf[q * CDIM + c] = pi[c];
    }

    // pi: 14 contiguous floats (genes g0, g0+1), 8B-aligned -> 7 x STG.64
    float2* pio = reinterpret_cast<float2*>(out + OFF_PI + e0 * 7);
#pragma unroll
    for (int j = 0; j < 7; j++)
        pio[j] = make_float2(buf[2 * j], buf[2 * j + 1]);

    const float2 wsv = *reinterpret_cast<const float2*>(ws + g0);
    const float2 bsv = *reinterpret_cast<const float2*>(bs + g0);
    *reinterpret_cast<float2*>(out + OFF_SAMP + e0) = make_float2(sm[0], sm[1]);
    float2 muv;
    muv.x = 1.0f / (1.0f + __expf(-fmaf(sm[0], wsv.x, bsv.x)));
    muv.y = 1.0f / (1.0f + __expf(-fmaf(sm[1], wsv.y, bsv.y)));
    *reinterpret_cast<float2*>(out + e0) = muv;
}

// ---------------------------------------------------------------------------
extern "C" void kernel_launch(void* const* d_in, const int* in_sizes, int n_in,
                              void* d_out, int out_size) {
    const float* z   = (const float*)d_in[0];
    const float* w0  = (const float*)d_in[1];
    const float* b0  = (const float*)d_in[2];
    const float* gm0 = (const float*)d_in[3];
    const float* be0 = (const float*)d_in[4];
    const float* m0  = (const float*)d_in[5];
    const float* v0  = (const float*)d_in[6];
    const float* w1  = (const float*)d_in[7];
    const float* b1  = (const float*)d_in[8];
    const float* gm1 = (const float*)d_in[9];
    const float* be1 = (const float*)d_in[10];
    const float* m1  = (const float*)d_in[11];
    const float* v1  = (const float*)d_in[12];
    const float* wr  = (const float*)d_in[13];
    const float* br  = (const float*)d_in[14];
    const float* wd  = (const float*)d_in[15];
    const float* bd  = (const float*)d_in[16];
    const float* wrho = (const float*)d_in[17];
    const float* brho = (const float*)d_in[18];
    const float* ws  = (const float*)d_in[19];
    const float* bs  = (const float*)d_in[20];
    float* out = (float*)d_out;

    float* rlog_ptr = nullptr;
    cudaGetSymbolAddress((void**)&rlog_ptr, g_rlog);

    // Order: mlp, rho, softmax, BIG_GEMM (position 4 -> ncu capture), gumbel.
    mlp_kernel<<<BDIM, HID>>>(z, w0, b0, gm0, be0, m0, v0,
                              w1, b1, gm1, be1, m1, v1);

    // all 7 rho heads: m-tile 128 -> grid (16, 2, 7)
    rho_gemm_kernel<<<dim3((GBD + 63) / 64, 2, CDIM), 256>>>(wrho, brho, rlog_ptr);

    rho_softmax_kernel<<<(NS + 255) / 256, 256>>>();

    // theta + pi_drop: m-tile 128 -> grid (391, 2, 2)
    big_gemm_kernel<<<dim3((GDIM + 63) / 64, 2, 2), 256>>>(wr, br, wd, bd, out);

    gumbel_kernel<<<dim3((GDIM / 2 + 255) / 256, 256), 256>>>(ws, bs, out);
}

// round 12
// speedup vs baseline: 1.1441x; 1.0823x over previous
#include <cuda_runtime.h>
#include <cstdint>
#include <math.h>

#define BDIM 256
#define LATD 20
#define HID 128
#define GDIM 25000
#define CDIM 7
#define GBD 1000
#define NS (BDIM * GBD)   // 256000 bins total

// Output layout (float32, flattened tuple in order):
//   mu      [256,25000]    @ 0
//   theta   [256,25000]    @ 6400000
//   pi_drop [256,25000]    @ 12800000
//   sample  [256,25000]    @ 19200000
//   pi      [256,25000,7]  @ 25600000
#define OFF_THETA  6400000
#define OFF_PDROP 12800000
#define OFF_SAMP  19200000
#define OFF_PI    25600000

// Scratch (device globals: no allocation allowed)
__device__ float g_xT[HID * BDIM];      // x transposed: [h][b]
__device__ float g_rlog[CDIM * NS];     // rho logits [c][b*GB]
__device__ float4 g_pib[NS * 4];        // per-bin struct: {pi[7], ipi[7], pad2}

typedef unsigned long long ull;

// Packed fp32x2 ops (sm_103a FFMA2 — only reachable via PTX)
#define FMA_F32X2(d, a, b, c) \
    asm("fma.rn.f32x2 %0, %1, %2, %3;" : "=l"(d) : "l"(a), "l"(b), "l"(c))
#define PACK_DUP_F32X2(d, s) \
    asm("mov.b64 %0, {%1, %1};" : "=l"(d) : "r"(__float_as_uint(s)))

// ---------------------------------------------------------------------------
// JAX threefry2x32, key = (0, 42), 20 rounds, partitionable mode:
//   bits32(i) = o0 ^ o1 where (o0,o1) = threefry(key, 0, i)
// ---------------------------------------------------------------------------
__device__ __forceinline__ unsigned threefry_xor(unsigned x0, unsigned x1) {
    const unsigned ks0 = 0u;
    const unsigned ks1 = 42u;
    const unsigned ks2 = 0x1BD11BDAu ^ 0u ^ 42u;
    x0 += ks0; x1 += ks1;
#define TFR(r) { x0 += x1; x1 = __funnelshift_l(x1, x1, (r)); x1 ^= x0; }
    TFR(13) TFR(15) TFR(26) TFR(6)
    x0 += ks1; x1 += ks2 + 1u;
    TFR(17) TFR(29) TFR(16) TFR(24)
    x0 += ks2; x1 += ks0 + 2u;
    TFR(13) TFR(15) TFR(26) TFR(6)
    x0 += ks0; x1 += ks1 + 3u;
    TFR(17) TFR(29) TFR(16) TFR(24)
    x0 += ks1; x1 += ks2 + 4u;
    TFR(13) TFR(15) TFR(26) TFR(6)
    x0 += ks2; x1 += ks0 + 5u;
#undef TFR
    return x0 ^ x1;
}

__device__ __forceinline__ float u01(unsigned bits) {
    return __uint_as_float((bits >> 9) | 0x3f800000u) - 1.0f;
}

// ---------------------------------------------------------------------------
// K1: tiny MLP.  grid(256), block(128).  Writes x transposed -> g_xT[h][b]
// ---------------------------------------------------------------------------
__global__ void mlp_kernel(const float* __restrict__ z,
                           const float* __restrict__ w0, const float* __restrict__ b0,
                           const float* __restrict__ gm0, const float* __restrict__ be0,
                           const float* __restrict__ m0, const float* __restrict__ v0,
                           const float* __restrict__ w1, const float* __restrict__ b1,
                           const float* __restrict__ gm1, const float* __restrict__ be1,
                           const float* __restrict__ m1, const float* __restrict__ v1) {
    __shared__ float zs[LATD];
    __shared__ float s0[HID];
    const int b = blockIdx.x, h = threadIdx.x;
    if (h < LATD) zs[h] = z[b * LATD + h];
    __syncthreads();
    float t = b0[h];
#pragma unroll
    for (int k = 0; k < LATD; k++) t = fmaf(zs[k], w0[k * HID + h], t);
    t = (t - m0[h]) * rsqrtf(v0[h] + 1e-3f) * gm0[h] + be0[h];
    s0[h] = fmaxf(t, 0.0f);
    __syncthreads();
    float t2 = b1[h];
#pragma unroll
    for (int k = 0; k < HID; k++) t2 = fmaf(s0[k], w1[k * HID + h], t2);
    t2 = (t2 - m1[h]) * rsqrtf(v1[h] + 1e-3f) * gm1[h] + be1[h];
    g_xT[h * BDIM + b] = fmaxf(t2, 0.0f);
}

// ---------------------------------------------------------------------------
// GEMM core: one 128m x 128n output tile of X[256,128] @ W[128,N] + bias.
// 256 threads, 8m x 8n per thread. Per k: 2 LDG.128 (x, broadcast) +
// 2 LDS.128 feed 32 FFMA2 (2x the old FMA:L1tex ratio — the issue-rate wall
// seen at 64n). W staged per 64-k chunk in two 16KB arrays Wa (n 0..63) /
// Wb (n 64..127): 16B thread stride -> conflict-free LDS (R7 lesson).
// Each FFMA2 lane = one column's full sequential k-sum: rounding identical
// to the R5/R8 epilogue.
// ---------------------------------------------------------------------------
template <int ACT>
__device__ __forceinline__ void gemm_tile(float* __restrict__ Wa,  // [64*64]
                                          float* __restrict__ Wb,  // [64*64]
                                          const float* __restrict__ W,
                                          const float* __restrict__ bias,
                                          float* __restrict__ out,
                                          int N, int n0, int m0) {
    const int tid = threadIdx.x;
    const int tn = (tid & 15) << 2;   // 0..60 (4-col group in each half)
    const int tm = (tid >> 4) << 3;   // 0..120 (8 m rows)
    ull acc[8][4] = {};
    const float* xb = g_xT + m0 + tm;

#pragma unroll
    for (int kc = 0; kc < 2; kc++) {
        if (kc) __syncthreads();  // all warps done with previous chunk
        // stage W[kc*64 .. +64)[n0 .. n0+128): 2048 float4 / 256 threads = 8
#pragma unroll
        for (int t = 0; t < 8; t++) {
            const int f = tid + t * 256;
            const int k = f >> 5;            // 0..63
            const int j4 = (f & 31) << 2;    // 0..124
            const int n = n0 + j4;
            float4 v = make_float4(0.f, 0.f, 0.f, 0.f);
            if (n < N)
                v = *reinterpret_cast<const float4*>(
                        W + (size_t)(kc * 64 + k) * N + n);
            float* dst = (j4 < 64) ? (Wa + k * 64 + j4)
                                   : (Wb + k * 64 + (j4 - 64));
            *reinterpret_cast<float4*>(dst) = v;
        }
        __syncthreads();

        const float* xc = xb + (size_t)(kc * 64) * BDIM;
        float4 av0 = __ldg(reinterpret_cast<const float4*>(xc));
        float4 av1 = __ldg(reinterpret_cast<const float4*>(xc + 4));
        float4 wv0 = *reinterpret_cast<const float4*>(Wa + tn);
        float4 wv1 = *reinterpret_cast<const float4*>(Wb + tn);

#pragma unroll 2
        for (int k = 0; k < 64; k++) {
            const int kn = (k < 63) ? k + 1 : 63;
            const float* xn = xc + (size_t)kn * BDIM;
            float4 nav0 = __ldg(reinterpret_cast<const float4*>(xn));
            float4 nav1 = __ldg(reinterpret_cast<const float4*>(xn + 4));
            float4 nwv0 = *reinterpret_cast<const float4*>(Wa + kn * 64 + tn);
            float4 nwv1 = *reinterpret_cast<const float4*>(Wb + kn * 64 + tn);

            const ull b0 = reinterpret_cast<const ull*>(&wv0)[0];
            const ull b1 = reinterpret_cast<const ull*>(&wv0)[1];
            const ull b2 = reinterpret_cast<const ull*>(&wv1)[0];
            const ull b3 = reinterpret_cast<const ull*>(&wv1)[1];
            const float a[8] = {av0.x, av0.y, av0.z, av0.w,
                                av1.x, av1.y, av1.z, av1.w};
#pragma unroll
            for (int i = 0; i < 8; i++) {
                ull ap;
                PACK_DUP_F32X2(ap, a[i]);
                FMA_F32X2(acc[i][0], ap, b0, acc[i][0]);
                FMA_F32X2(acc[i][1], ap, b1, acc[i][1]);
                FMA_F32X2(acc[i][2], ap, b2, acc[i][2]);
                FMA_F32X2(acc[i][3], ap, b3, acc[i][3]);
            }
            av0 = nav0; av1 = nav1; wv0 = nwv0; wv1 = nwv1;
        }
    }

    // epilogue: two guarded 4-col halves per m row
    const int c0 = n0 + tn;
    const int c1 = n0 + 64 + tn;
    if (c0 < N) {
        const float4 bv = *reinterpret_cast<const float4*>(bias + c0);
#pragma unroll
        for (int i = 0; i < 8; i++) {
            const int m = m0 + tm + i;
            float2 lo = *reinterpret_cast<float2*>(&acc[i][0]);
            float2 hi = *reinterpret_cast<float2*>(&acc[i][1]);
            float4 r;
            r.x = lo.x + bv.x; r.y = lo.y + bv.y;
            r.z = hi.x + bv.z; r.w = hi.y + bv.w;
            if (ACT == 1) {
                r.x = __expf(r.x); r.y = __expf(r.y);
                r.z = __expf(r.z); r.w = __expf(r.w);
            }
            *reinterpret_cast<float4*>(out + (size_t)m * N + c0) = r;
        }
    }
    if (c1 < N) {
        const float4 bv = *reinterpret_cast<const float4*>(bias + c1);
#pragma unroll
        for (int i = 0; i < 8; i++) {
            const int m = m0 + tm + i;
            float2 lo = *reinterpret_cast<float2*>(&acc[i][2]);
            float2 hi = *reinterpret_cast<float2*>(&acc[i][3]);
            float4 r;
            r.x = lo.x + bv.x; r.y = lo.y + bv.y;
            r.z = hi.x + bv.z; r.w = hi.y + bv.w;
            if (ACT == 1) {
                r.x = __expf(r.x); r.y = __expf(r.y);
                r.z = __expf(r.z); r.w = __expf(r.w);
            }
            *reinterpret_cast<float4*>(out + (size_t)m * N + c1) = r;
        }
    }
}

// K2a: theta (exp) + pi_drop in one launch. z=0 -> theta, z=1 -> pi_drop.
__global__ void __launch_bounds__(256, 2) big_gemm_kernel(
        const float* __restrict__ wr, const float* __restrict__ br,
        const float* __restrict__ wd, const float* __restrict__ bd,
        float* __restrict__ out) {
    __shared__ float Wa[64 * 64];
    __shared__ float Wb[64 * 64];
    const int n0 = blockIdx.x * 128;
    const int m0 = blockIdx.y * 128;
    if (blockIdx.z == 0)
        gemm_tile<1>(Wa, Wb, wr, br, out + OFF_THETA, GDIM, n0, m0);
    else
        gemm_tile<0>(Wa, Wb, wd, bd, out + OFF_PDROP, GDIM, n0, m0);
}

// K2b: all 7 rho heads in one launch. z = copy-number state c.
__global__ void __launch_bounds__(256, 2) rho_gemm_kernel(
        const float* __restrict__ wrho, const float* __restrict__ brho,
        float* __restrict__ rlog) {
    __shared__ float Wa[64 * 64];
    __shared__ float Wb[64 * 64];
    const int c = blockIdx.z;
    const int n0 = blockIdx.x * 128;
    const int m0 = blockIdx.y * 128;
    gemm_tile<0>(Wa, Wb, wrho + (size_t)c * HID * GBD, brho + (size_t)c * GBD,
                 rlog + (size_t)c * BDIM * GBD, GBD, n0, m0);
}

// ---------------------------------------------------------------------------
// K3: softmax over the C=7 copy-number states (accurate expf; pi feeds the
// sampler's ordering with no fallback protection). Writes one 64B struct
// per bin: {pi[0..6], ipi[0..6], pad, pad} as 4 x float4.
// ---------------------------------------------------------------------------
__global__ void rho_softmax_kernel() {
    const int i = blockIdx.x * 256 + threadIdx.x;  // over B*GB = 256000
    if (i >= NS) return;
    float l[CDIM];
    float mx = -3.402823466e38f;
#pragma unroll
    for (int c = 0; c < CDIM; c++) {
        l[c] = g_rlog[c * NS + i];
        mx = fmaxf(mx, l[c]);
    }
    float s = 0.0f;
#pragma unroll
    for (int c = 0; c < CDIM; c++) { l[c] = expf(l[c] - mx); s += l[c]; }
    float v[16];
#pragma unroll
    for (int c = 0; c < CDIM; c++) {
        const float pe = l[c] / s;
        v[c] = pe;
        v[7 + c] = 1.0f / (pe + 1e-20f);
    }
    v[14] = 0.f; v[15] = 0.f;
    float4* dst = &g_pib[(size_t)i * 4];
    dst[0] = make_float4(v[0],  v[1],  v[2],  v[3]);
    dst[1] = make_float4(v[4],  v[5],  v[6],  v[7]);
    dst[2] = make_float4(v[8],  v[9],  v[10], v[11]);
    dst[3] = make_float4(v[12], v[13], v[14], v[15]);
}

// ---------------------------------------------------------------------------
// K4: Gumbel straight-through sampler. 2 adjacent genes per thread.
// Fast path: argmin_c nl_c * ipi_c with nl via MUFU __logf (off the fma pipe).
// Robust fallback: if top-2 gap < 1e-4*w2 + 4e-6 (>=20x worst-case __logf
// error), redo ordering with the exact accurate-logf reference formula.
// (Measured R7: 141.6us, alu=89.7% — at its threefry alu floor. Unchanged.)
// ---------------------------------------------------------------------------
__global__ void __launch_bounds__(256) gumbel_kernel(const float* __restrict__ ws,
                                                     const float* __restrict__ bs,
                                                     float* __restrict__ out) {
    const int t = blockIdx.x * 256 + threadIdx.x;
    const int g0 = t * 2;
    if (g0 >= GDIM) return;
    const int b = blockIdx.y;  // 0..255
    const size_t e0 = (size_t)b * GDIM + g0;

    float buf[14];
    float sm[2];
#pragma unroll
    for (int q = 0; q < 2; q++) {
        const int g = g0 + q;
        const int i0 = b * GBD + g / 25;
        const float4* pbp = &g_pib[(size_t)i0 * 4];
        const float4 L0 = __ldg(pbp + 0);
        const float4 L1 = __ldg(pbp + 1);
        const float4 L2 = __ldg(pbp + 2);
        const float4 L3 = __ldg(pbp + 3);
        const float pi[CDIM] = {L0.x, L0.y, L0.z, L0.w, L1.x, L1.y, L1.z};
        const float ip[CDIM] = {L1.w, L2.x, L2.y, L2.z, L2.w, L3.x, L3.y};
        const unsigned base = ((unsigned)b * (unsigned)GDIM + (unsigned)g) * 7u;
        float u[CDIM];
        float w1 = 3.402823466e38f, w2 = 3.402823466e38f;
        int amin = 0;
#pragma unroll
        for (int c = 0; c < CDIM; c++) {
            u[c] = u01(threefry_xor(0u, base + (unsigned)c));
            const float w = -__logf(u[c] + 1e-20f) * ip[c];
            if (w < w1) { w2 = w1; w1 = w; amin = c; }
            else if (w < w2) { w2 = w; }
        }
        if (w2 - w1 < 1e-4f * w2 + 4e-6f) {
            // exact reference-formula ordering (accurate logf) for near-ties
            float best = -3.402823466e38f;
            amin = 0;
#pragma unroll
            for (int c = 0; c < CDIM; c++) {
                const float nle = -logf(u[c] + 1e-20f) + 1e-20f;
                const float l = logf(pi[c] + 1e-20f) - logf(nle);
                if (l > best) { best = l; amin = c; }
            }
        }
        sm[q] = (float)amin;
#pragma unroll
        for (int c = 0; c < CDIM; c++) buf[q * CDIM + c] = pi[c];
    }

    // pi: 14 contiguous floats (genes g0, g0+1), 8B-aligned -> 7 x STG.64
    float2* pio = reinterpret_cast<float2*>(out + OFF_PI + e0 * 7);
#pragma unroll
    for (int j = 0; j < 7; j++)
        pio[j] = make_float2(buf[2 * j], buf[2 * j + 1]);

    const float2 wsv = *reinterpret_cast<const float2*>(ws + g0);
    const float2 bsv = *reinterpret_cast<const float2*>(bs + g0);
    *reinterpret_cast<float2*>(out + OFF_SAMP + e0) = make_float2(sm[0], sm[1]);
    float2 muv;
    muv.x = 1.0f / (1.0f + __expf(-fmaf(sm[0], wsv.x, bsv.x)));
    muv.y = 1.0f / (1.0f + __expf(-fmaf(sm[1], wsv.y, bsv.y)));
    *reinterpret_cast<float2*>(out + e0) = muv;
}

// ---------------------------------------------------------------------------
extern "C" void kernel_launch(void* const* d_in, const int* in_sizes, int n_in,
                              void* d_out, int out_size) {
    const float* z   = (const float*)d_in[0];
    const float* w0  = (const float*)d_in[1];
    const float* b0  = (const float*)d_in[2];
    const float* gm0 = (const float*)d_in[3];
    const float* be0 = (const float*)d_in[4];
    const float* m0  = (const float*)d_in[5];
    const float* v0  = (const float*)d_in[6];
    const float* w1  = (const float*)d_in[7];
    const float* b1  = (const float*)d_in[8];
    const float* gm1 = (const float*)d_in[9];
    const float* be1 = (const float*)d_in[10];
    const float* m1  = (const float*)d_in[11];
    const float* v1  = (const float*)d_in[12];
    const float* wr  = (const float*)d_in[13];
    const float* br  = (const float*)d_in[14];
    const float* wd  = (const float*)d_in[15];
    const float* bd  = (const float*)d_in[16];
    const float* wrho = (const float*)d_in[17];
    const float* brho = (const float*)d_in[18];
    const float* ws  = (const float*)d_in[19];
    const float* bs  = (const float*)d_in[20];
    float* out = (float*)d_out;

    float* rlog_ptr = nullptr;
    cudaGetSymbolAddress((void**)&rlog_ptr, g_rlog);

    // Order: mlp, rho, softmax, BIG_GEMM (position 4 -> ncu capture), gumbel.
    mlp_kernel<<<BDIM, HID>>>(z, w0, b0, gm0, be0, m0, v0,
                              w1, b1, gm1, be1, m1, v1);

    // all 7 rho heads: 128n x 128m tiles -> grid (8, 2, 7)
    rho_gemm_kernel<<<dim3((GBD + 127) / 128, 2, CDIM), 256>>>(wrho, brho, rlog_ptr);

    rho_softmax_kernel<<<(NS + 255) / 256, 256>>>();

    // theta + pi_drop: grid (196, 2, 2)
    big_gemm_kernel<<<dim3((GDIM + 127) / 128, 2, 2), 256>>>(wr, br, wd, bd, out);

    gumbel_kernel<<<dim3((GDIM / 2 + 255) / 256, 256), 256>>>(ws, bs, out);
}

// round 15
// speedup vs baseline: 1.2342x; 1.0787x over previous
#include <cuda_runtime.h>
#include <cstdint>
#include <math.h>

#define BDIM 256
#define LATD 20
#define HID 128
#define GDIM 25000
#define CDIM 7
#define GBD 1000
#define NS (BDIM * GBD)   // 256000 bins total

// Output layout (float32, flattened tuple in order):
//   mu      [256,25000]    @ 0
//   theta   [256,25000]    @ 6400000
//   pi_drop [256,25000]    @ 12800000
//   sample  [256,25000]    @ 19200000
//   pi      [256,25000,7]  @ 25600000
#define OFF_THETA  6400000
#define OFF_PDROP 12800000
#define OFF_SAMP  19200000
#define OFF_PI    25600000

// Scratch (device globals: no allocation allowed)
__device__ float g_xT[HID * BDIM];      // x transposed: [h][b]
__device__ float g_rlog[CDIM * NS];     // rho logits [c][b*GB]
__device__ float4 g_pib[NS * 4];        // per-bin struct: {pi[7], ipi[7], pad2}

typedef unsigned long long ull;

// Packed fp32x2 ops (sm_103a FFMA2 — only reachable via PTX)
#define FMA_F32X2(d, a, b, c) \
    asm("fma.rn.f32x2 %0, %1, %2, %3;" : "=l"(d) : "l"(a), "l"(b), "l"(c))
#define PACK_DUP_F32X2(d, s) \
    asm("mov.b64 %0, {%1, %1};" : "=l"(d) : "r"(__float_as_uint(s)))

// ---------------------------------------------------------------------------
// JAX threefry2x32, key = (0, 42), 20 rounds, partitionable mode:
//   bits32(i) = o0 ^ o1 where (o0,o1) = threefry(key, 0, i)
// ---------------------------------------------------------------------------
__device__ __forceinline__ unsigned threefry_xor(unsigned x0, unsigned x1) {
    const unsigned ks0 = 0u;
    const unsigned ks1 = 42u;
    const unsigned ks2 = 0x1BD11BDAu ^ 0u ^ 42u;
    x0 += ks0; x1 += ks1;
#define TFR(r) { x0 += x1; x1 = __funnelshift_l(x1, x1, (r)); x1 ^= x0; }
    TFR(13) TFR(15) TFR(26) TFR(6)
    x0 += ks1; x1 += ks2 + 1u;
    TFR(17) TFR(29) TFR(16) TFR(24)
    x0 += ks2; x1 += ks0 + 2u;
    TFR(13) TFR(15) TFR(26) TFR(6)
    x0 += ks0; x1 += ks1 + 3u;
    TFR(17) TFR(29) TFR(16) TFR(24)
    x0 += ks1; x1 += ks2 + 4u;
    TFR(13) TFR(15) TFR(26) TFR(6)
    x0 += ks2; x1 += ks0 + 5u;
#undef TFR
    return x0 ^ x1;
}

__device__ __forceinline__ float u01(unsigned bits) {
    return __uint_as_float((bits >> 9) | 0x3f800000u) - 1.0f;
}

// ---------------------------------------------------------------------------
// K1: tiny MLP.  grid(256), block(128).  Writes x transposed -> g_xT[h][b]
// ---------------------------------------------------------------------------
__global__ void mlp_kernel(const float* __restrict__ z,
                           const float* __restrict__ w0, const float* __restrict__ b0,
                           const float* __restrict__ gm0, const float* __restrict__ be0,
                           const float* __restrict__ m0, const float* __restrict__ v0,
                           const float* __restrict__ w1, const float* __restrict__ b1,
                           const float* __restrict__ gm1, const float* __restrict__ be1,
                           const float* __restrict__ m1, const float* __restrict__ v1) {
    __shared__ float zs[LATD];
    __shared__ float s0[HID];
    const int b = blockIdx.x, h = threadIdx.x;
    if (h < LATD) zs[h] = z[b * LATD + h];
    __syncthreads();
    float t = b0[h];
#pragma unroll
    for (int k = 0; k < LATD; k++) t = fmaf(zs[k], w0[k * HID + h], t);
    t = (t - m0[h]) * rsqrtf(v0[h] + 1e-3f) * gm0[h] + be0[h];
    s0[h] = fmaxf(t, 0.0f);
    __syncthreads();
    float t2 = b1[h];
#pragma unroll
    for (int k = 0; k < HID; k++) t2 = fmaf(s0[k], w1[k * HID + h], t2);
    t2 = (t2 - m1[h]) * rsqrtf(v1[h] + 1e-3f) * gm1[h] + be1[h];
    g_xT[h * BDIM + b] = fmaxf(t2, 0.0f);
}

// ---------------------------------------------------------------------------
// GEMM core: one 128m x 128n output tile of X[256,128] @ W[128,N] + bias.
// 256 threads, 8m x 8n per thread. Per k: 2 LDG.128 (x, broadcast) +
// 2 LDS.128 feed 32 FFMA2. W staged per 64-k chunk in two 16KB arrays
// (16B thread stride -> conflict-free LDS). Measured R12: 83.3us, fma=51.3%.
// ---------------------------------------------------------------------------
template <int ACT>
__device__ __forceinline__ void gemm_tile(float* __restrict__ Wa,  // [64*64]
                                          float* __restrict__ Wb,  // [64*64]
                                          const float* __restrict__ W,
                                          const float* __restrict__ bias,
                                          float* __restrict__ out,
                                          int N, int n0, int m0) {
    const int tid = threadIdx.x;
    const int tn = (tid & 15) << 2;   // 0..60 (4-col group in each half)
    const int tm = (tid >> 4) << 3;   // 0..120 (8 m rows)
    ull acc[8][4] = {};
    const float* xb = g_xT + m0 + tm;

#pragma unroll
    for (int kc = 0; kc < 2; kc++) {
        if (kc) __syncthreads();  // all warps done with previous chunk
        // stage W[kc*64 .. +64)[n0 .. n0+128): 2048 float4 / 256 threads = 8
#pragma unroll
        for (int t = 0; t < 8; t++) {
            const int f = tid + t * 256;
            const int k = f >> 5;            // 0..63
            const int j4 = (f & 31) << 2;    // 0..124
            const int n = n0 + j4;
            float4 v = make_float4(0.f, 0.f, 0.f, 0.f);
            if (n < N)
                v = *reinterpret_cast<const float4*>(
                        W + (size_t)(kc * 64 + k) * N + n);
            float* dst = (j4 < 64) ? (Wa + k * 64 + j4)
                                   : (Wb + k * 64 + (j4 - 64));
            *reinterpret_cast<float4*>(dst) = v;
        }
        __syncthreads();

        const float* xc = xb + (size_t)(kc * 64) * BDIM;
        float4 av0 = __ldg(reinterpret_cast<const float4*>(xc));
        float4 av1 = __ldg(reinterpret_cast<const float4*>(xc + 4));
        float4 wv0 = *reinterpret_cast<const float4*>(Wa + tn);
        float4 wv1 = *reinterpret_cast<const float4*>(Wb + tn);

#pragma unroll 2
        for (int k = 0; k < 64; k++) {
            const int kn = (k < 63) ? k + 1 : 63;
            const float* xn = xc + (size_t)kn * BDIM;
            float4 nav0 = __ldg(reinterpret_cast<const float4*>(xn));
            float4 nav1 = __ldg(reinterpret_cast<const float4*>(xn + 4));
            float4 nwv0 = *reinterpret_cast<const float4*>(Wa + kn * 64 + tn);
            float4 nwv1 = *reinterpret_cast<const float4*>(Wb + kn * 64 + tn);

            const ull b0 = reinterpret_cast<const ull*>(&wv0)[0];
            const ull b1 = reinterpret_cast<const ull*>(&wv0)[1];
            const ull b2 = reinterpret_cast<const ull*>(&wv1)[0];
            const ull b3 = reinterpret_cast<const ull*>(&wv1)[1];
            const float a[8] = {av0.x, av0.y, av0.z, av0.w,
                                av1.x, av1.y, av1.z, av1.w};
#pragma unroll
            for (int i = 0; i < 8; i++) {
                ull ap;
                PACK_DUP_F32X2(ap, a[i]);
                FMA_F32X2(acc[i][0], ap, b0, acc[i][0]);
                FMA_F32X2(acc[i][1], ap, b1, acc[i][1]);
                FMA_F32X2(acc[i][2], ap, b2, acc[i][2]);
                FMA_F32X2(acc[i][3], ap, b3, acc[i][3]);
            }
            av0 = nav0; av1 = nav1; wv0 = nwv0; wv1 = nwv1;
        }
    }

    // epilogue: two guarded 4-col halves per m row
    const int c0 = n0 + tn;
    const int c1 = n0 + 64 + tn;
    if (c0 < N) {
        const float4 bv = *reinterpret_cast<const float4*>(bias + c0);
#pragma unroll
        for (int i = 0; i < 8; i++) {
            const int m = m0 + tm + i;
            float2 lo = *reinterpret_cast<float2*>(&acc[i][0]);
            float2 hi = *reinterpret_cast<float2*>(&acc[i][1]);
            float4 r;
            r.x = lo.x + bv.x; r.y = lo.y + bv.y;
            r.z = hi.x + bv.z; r.w = hi.y + bv.w;
            if (ACT == 1) {
                r.x = __expf(r.x); r.y = __expf(r.y);
                r.z = __expf(r.z); r.w = __expf(r.w);
            }
            *reinterpret_cast<float4*>(out + (size_t)m * N + c0) = r;
        }
    }
    if (c1 < N) {
        const float4 bv = *reinterpret_cast<const float4*>(bias + c1);
#pragma unroll
        for (int i = 0; i < 8; i++) {
            const int m = m0 + tm + i;
            float2 lo = *reinterpret_cast<float2*>(&acc[i][2]);
            float2 hi = *reinterpret_cast<float2*>(&acc[i][3]);
            float4 r;
            r.x = lo.x + bv.x; r.y = lo.y + bv.y;
            r.z = hi.x + bv.z; r.w = hi.y + bv.w;
            if (ACT == 1) {
                r.x = __expf(r.x); r.y = __expf(r.y);
                r.z = __expf(r.z); r.w = __expf(r.w);
            }
            *reinterpret_cast<float4*>(out + (size_t)m * N + c1) = r;
        }
    }
}

// K2a: theta (exp) + pi_drop in one launch. z=0 -> theta, z=1 -> pi_drop.
__global__ void __launch_bounds__(256, 2) big_gemm_kernel(
        const float* __restrict__ wr, const float* __restrict__ br,
        const float* __restrict__ wd, const float* __restrict__ bd,
        float* __restrict__ out) {
    __shared__ float Wa[64 * 64];
    __shared__ float Wb[64 * 64];
    const int n0 = blockIdx.x * 128;
    const int m0 = blockIdx.y * 128;
    if (blockIdx.z == 0)
        gemm_tile<1>(Wa, Wb, wr, br, out + OFF_THETA, GDIM, n0, m0);
    else
        gemm_tile<0>(Wa, Wb, wd, bd, out + OFF_PDROP, GDIM, n0, m0);
}

// K2b: all 7 rho heads in one launch. z = copy-number state c.
__global__ void __launch_bounds__(256, 2) rho_gemm_kernel(
        const float* __restrict__ wrho, const float* __restrict__ brho,
        float* __restrict__ rlog) {
    __shared__ float Wa[64 * 64];
    __shared__ float Wb[64 * 64];
    const int c = blockIdx.z;
    const int n0 = blockIdx.x * 128;
    const int m0 = blockIdx.y * 128;
    gemm_tile<0>(Wa, Wb, wrho + (size_t)c * HID * GBD, brho + (size_t)c * GBD,
                 rlog + (size_t)c * BDIM * GBD, GBD, n0, m0);
}

// ---------------------------------------------------------------------------
// K3: softmax over the C=7 copy-number states (accurate expf; pi feeds the
// sampler's ordering with no fallback protection). Writes one 64B struct
// per bin: {pi[0..6], ipi[0..6], pad, pad} as 4 x float4.
// ---------------------------------------------------------------------------
__global__ void rho_softmax_kernel() {
    const int i = blockIdx.x * 256 + threadIdx.x;  // over B*GB = 256000
    if (i >= NS) return;
    float l[CDIM];
    float mx = -3.402823466e38f;
#pragma unroll
    for (int c = 0; c < CDIM; c++) {
        l[c] = g_rlog[c * NS + i];
        mx = fmaxf(mx, l[c]);
    }
    float s = 0.0f;
#pragma unroll
    for (int c = 0; c < CDIM; c++) { l[c] = expf(l[c] - mx); s += l[c]; }
    float v[16];
#pragma unroll
    for (int c = 0; c < CDIM; c++) {
        const float pe = l[c] / s;
        v[c] = pe;
        v[7 + c] = 1.0f / (pe + 1e-20f);
    }
    v[14] = 0.f; v[15] = 0.f;
    float4* dst = &g_pib[(size_t)i * 4];
    dst[0] = make_float4(v[0],  v[1],  v[2],  v[3]);
    dst[1] = make_float4(v[4],  v[5],  v[6],  v[7]);
    dst[2] = make_float4(v[8],  v[9],  v[10], v[11]);
    dst[3] = make_float4(v[12], v[13], v[14], v[15]);
}

// ---------------------------------------------------------------------------
// K4: Gumbel straight-through sampler. 2 adjacent genes per thread.
// Fast path: argmin_c nl_c * ipi_c with nl via MUFU __logf (off the fma pipe).
// Robust fallback: if top-2 gap < 1e-4*w2 + 4e-6 (>=20x worst-case __logf
// error), redo ordering with the exact accurate-logf reference formula.
// (Measured R7: 141.6us, alu=89.7% — at its threefry alu floor. Unchanged.)
// ---------------------------------------------------------------------------
__global__ void __launch_bounds__(256) gumbel_kernel(const float* __restrict__ ws,
                                                     const float* __restrict__ bs,
                                                     float* __restrict__ out) {
    const int t = blockIdx.x * 256 + threadIdx.x;
    const int g0 = t * 2;
    if (g0 >= GDIM) return;
    const int b = blockIdx.y;  // 0..255
    const size_t e0 = (size_t)b * GDIM + g0;

    float buf[14];
    float sm[2];
#pragma unroll
    for (int q = 0; q < 2; q++) {
        const int g = g0 + q;
        const int i0 = b * GBD + g / 25;
        const float4* pbp = &g_pib[(size_t)i0 * 4];
        const float4 L0 = __ldg(pbp + 0);
        const float4 L1 = __ldg(pbp + 1);
        const float4 L2 = __ldg(pbp + 2);
        const float4 L3 = __ldg(pbp + 3);
        const float pi[CDIM] = {L0.x, L0.y, L0.z, L0.w, L1.x, L1.y, L1.z};
        const float ip[CDIM] = {L1.w, L2.x, L2.y, L2.z, L2.w, L3.x, L3.y};
        const unsigned base = ((unsigned)b * (unsigned)GDIM + (unsigned)g) * 7u;
        float u[CDIM];
        float w1 = 3.402823466e38f, w2 = 3.402823466e38f;
        int amin = 0;
#pragma unroll
        for (int c = 0; c < CDIM; c++) {
            u[c] = u01(threefry_xor(0u, base + (unsigned)c));
            const float w = -__logf(u[c] + 1e-20f) * ip[c];
            if (w < w1) { w2 = w1; w1 = w; amin = c; }
            else if (w < w2) { w2 = w; }
        }
        if (w2 - w1 < 1e-4f * w2 + 4e-6f) {
            // exact reference-formula ordering (accurate logf) for near-ties
            float best = -3.402823466e38f;
            amin = 0;
#pragma unroll
            for (int c = 0; c < CDIM; c++) {
                const float nle = -logf(u[c] + 1e-20f) + 1e-20f;
                const float l = logf(pi[c] + 1e-20f) - logf(nle);
                if (l > best) { best = l; amin = c; }
            }
        }
        sm[q] = (float)amin;
#pragma unroll
        for (int c = 0; c < CDIM; c++) buf[q * CDIM + c] = pi[c];
    }

    // pi: 14 contiguous floats (genes g0, g0+1), 8B-aligned -> 7 x STG.64
    float2* pio = reinterpret_cast<float2*>(out + OFF_PI + e0 * 7);
#pragma unroll
    for (int j = 0; j < 7; j++)
        pio[j] = make_float2(buf[2 * j], buf[2 * j + 1]);

    const float2 wsv = *reinterpret_cast<const float2*>(ws + g0);
    const float2 bsv = *reinterpret_cast<const float2*>(bs + g0);
    *reinterpret_cast<float2*>(out + OFF_SAMP + e0) = make_float2(sm[0], sm[1]);
    float2 muv;
    muv.x = 1.0f / (1.0f + __expf(-fmaf(sm[0], wsv.x, bsv.x)));
    muv.y = 1.0f / (1.0f + __expf(-fmaf(sm[1], wsv.y, bsv.y)));
    *reinterpret_cast<float2*>(out + e0) = muv;
}

// ---------------------------------------------------------------------------
// Two-stream fork/join: big_gemm (fma-bound) runs concurrently with
// rho->softmax->gumbel (alu-bound). Complementary pipes -> near-full overlap.
// Stream/event created once (host-side only, no device allocation); the
// launched work is identical on every call, so determinism and
// graph-capture (event fork/join from the capture-origin stream) both hold.
// ---------------------------------------------------------------------------
extern "C" void kernel_launch(void* const* d_in, const int* in_sizes, int n_in,
                              void* d_out, int out_size) {
    const float* z   = (const float*)d_in[0];
    const float* w0  = (const float*)d_in[1];
    const float* b0  = (const float*)d_in[2];
    const float* gm0 = (const float*)d_in[3];
    const float* be0 = (const float*)d_in[4];
    const float* m0  = (const float*)d_in[5];
    const float* v0  = (const float*)d_in[6];
    const float* w1  = (const float*)d_in[7];
    const float* b1  = (const float*)d_in[8];
    const float* gm1 = (const float*)d_in[9];
    const float* be1 = (const float*)d_in[10];
    const float* m1  = (const float*)d_in[11];
    const float* v1  = (const float*)d_in[12];
    const float* wr  = (const float*)d_in[13];
    const float* br  = (const float*)d_in[14];
    const float* wd  = (const float*)d_in[15];
    const float* bd  = (const float*)d_in[16];
    const float* wrho = (const float*)d_in[17];
    const float* brho = (const float*)d_in[18];
    const float* ws  = (const float*)d_in[19];
    const float* bs  = (const float*)d_in[20];
    float* out = (float*)d_out;

    float* rlog_ptr = nullptr;
    cudaGetSymbolAddress((void**)&rlog_ptr, g_rlog);

    static cudaStream_t s2 = nullptr;
    static cudaEvent_t ev_mlp = nullptr, ev_gemm = nullptr;
    if (s2 == nullptr) {
        cudaStreamCreateWithFlags(&s2, cudaStreamNonBlocking);
        cudaEventCreateWithFlags(&ev_mlp, cudaEventDisableTiming);
        cudaEventCreateWithFlags(&ev_gemm, cudaEventDisableTiming);
    }

    // K1 on the origin stream: both chains depend on g_xT.
    mlp_kernel<<<BDIM, HID>>>(z, w0, b0, gm0, be0, m0, v0,
                              w1, b1, gm1, be1, m1, v1);
    cudaEventRecord(ev_mlp, 0);

    // Fork: theta + pi_drop GEMM on s2 (fma-bound, 83us).
    cudaStreamWaitEvent(s2, ev_mlp, 0);
    big_gemm_kernel<<<dim3((GDIM + 127) / 128, 2, 2), 256, 0, s2>>>(
        wr, br, wd, bd, out);
    cudaEventRecord(ev_gemm, s2);

    // Origin stream: rho -> softmax -> gumbel (alu-bound chain, ~160us).
    rho_gemm_kernel<<<dim3((GBD + 127) / 128, 2, CDIM), 256>>>(wrho, brho, rlog_ptr);
    rho_softmax_kernel<<<(NS + 255) / 256, 256>>>();
    gumbel_kernel<<<dim3((GDIM / 2 + 255) / 256, 256), 256>>>(ws, bs, out);

    // Join: origin stream waits for the GEMM branch before returning.
    cudaStreamWaitEvent(0, ev_gemm, 0);
}